// round 1
// baseline (speedup 1.0000x reference)
#include <cuda_runtime.h>
#include <math.h>

// Problem constants (from reference: B=8, C=128, N=8192, K=9, PAD=4, DIL=1, STR=1, L=N)
#define Bv 8
#define Cv 128
#define Nv 8192
#define Kv 9
#define HALF_K 4           // K/2
#define TL 128             // l positions per block tile
#define THREADS 256
#define C_PER_BLOCK 32     // channels handled per block (grid.z = Cv / C_PER_BLOCK)

__global__ __launch_bounds__(THREADS)
void swconv_kernel(const float* __restrict__ x,
                   const float* __restrict__ coords,
                   const float* __restrict__ sigma,
                   const float* __restrict__ weight,
                   float* __restrict__ out)
{
    __shared__ float dwT[Kv][TL];          // transposed: [k][l] -> aligned float4 reads
    __shared__ float ws[C_PER_BLOCK * Kv]; // weights for this block's channel slice

    const int b    = blockIdx.y;
    const int l0g  = blockIdx.x * TL;           // global l of tile start
    const int cbase = blockIdx.z * C_PER_BLOCK; // first channel of this block
    const int tid  = threadIdx.x;

    // ---- load this block's weight slice into shared ----
    for (int i = tid; i < C_PER_BLOCK * Kv; i += THREADS)
        ws[i] = weight[cbase * Kv + i];

    // ---- phase 1: distance weights dw[l][k], channel-independent ----
    if (tid < TL) {
        const int l = l0g + tid;
        const float* cb = coords + (size_t)b * 3 * Nv;
        const float cx = cb[l];
        const float cy = cb[Nv + l];
        const float cz = cb[2 * Nv + l];
        const float inv_sig = 1.0f / sigma[0];
        #pragma unroll
        for (int k = 0; k < Kv; k++) {
            const int idx = l + k - HALF_K;
            float dx, dy, dz;
            if (idx >= 0 && idx < Nv) {
                dx = cb[idx]        - cx;
                dy = cb[Nv + idx]   - cy;
                dz = cb[2*Nv + idx] - cz;
            } else {
                // zero-padded coords
                dx = -cx; dy = -cy; dz = -cz;
            }
            const float sq   = dx*dx + dy*dy + dz*dz;
            const float dist = (sq > 0.0f) ? sqrtf(sq) : 0.0f;
            dwT[k][tid] = fmaxf(1.0f - dist * inv_sig, 0.0f);
        }
    }
    __syncthreads();

    // ---- phase 2: weighted depthwise conv ----
    // warp layout: lane -> 4-wide l group (32 lanes * 4 = 128 l), warp id -> channel offset
    const int quad = tid & 31;       // l-quad index within tile
    const int cofs = tid >> 5;       // 0..7
    const int lq   = quad * 4;       // local l of first output element
    const int lg   = l0g + lq;       // global l

    const bool interior = (l0g >= HALF_K) && (l0g + TL + HALF_K <= Nv);

    // dw quads are fixed for this thread across all channel iterations
    float4 dq[Kv];
    #pragma unroll
    for (int k = 0; k < Kv; k++)
        dq[k] = *reinterpret_cast<const float4*>(&dwT[k][lq]);

    #pragma unroll
    for (int ci = 0; ci < C_PER_BLOCK; ci += 8) {
        const int c = cbase + ci + cofs;
        const float* xb = x + ((size_t)(b * Cv + c)) * Nv;

        float xv[12];
        if (interior) {
            const float4 a = *reinterpret_cast<const float4*>(xb + lg - 4);
            const float4 m = *reinterpret_cast<const float4*>(xb + lg);
            const float4 r = *reinterpret_cast<const float4*>(xb + lg + 4);
            xv[0]=a.x; xv[1]=a.y; xv[2]=a.z;  xv[3]=a.w;
            xv[4]=m.x; xv[5]=m.y; xv[6]=m.z;  xv[7]=m.w;
            xv[8]=r.x; xv[9]=r.y; xv[10]=r.z; xv[11]=r.w;
        } else {
            #pragma unroll
            for (int j = 0; j < 12; j++) {
                const int idx = lg - 4 + j;
                xv[j] = (idx >= 0 && idx < Nv) ? xb[idx] : 0.0f;
            }
        }

        const float* wc = &ws[(ci + cofs) * Kv];
        float4 acc = make_float4(0.f, 0.f, 0.f, 0.f);
        #pragma unroll
        for (int k = 0; k < Kv; k++) {
            const float wk = wc[k];  // broadcast across warp (same c per warp)
            acc.x = fmaf(xv[k + 0] * dq[k].x, wk, acc.x);
            acc.y = fmaf(xv[k + 1] * dq[k].y, wk, acc.y);
            acc.z = fmaf(xv[k + 2] * dq[k].z, wk, acc.z);
            acc.w = fmaf(xv[k + 3] * dq[k].w, wk, acc.w);
        }

        *reinterpret_cast<float4*>(out + ((size_t)(b * Cv + c)) * Nv + lg) = acc;
    }
}

extern "C" void kernel_launch(void* const* d_in, const int* in_sizes, int n_in,
                              void* d_out, int out_size)
{
    const float* x      = (const float*)d_in[0]; // (8,128,8192,1)
    const float* coords = (const float*)d_in[1]; // (8,3,8192,1)
    const float* sigma  = (const float*)d_in[2]; // (1,)
    const float* weight = (const float*)d_in[3]; // (128,1,9)
    float* out = (float*)d_out;                  // (8,128,8192)

    dim3 grid(Nv / TL, Bv, Cv / C_PER_BLOCK);    // (64, 8, 4)
    swconv_kernel<<<grid, THREADS>>>(x, coords, sigma, weight, out);
}